// round 13
// baseline (speedup 1.0000x reference)
#include <cuda_runtime.h>
#include <cuda_bf16.h>
#include <cstdint>
#include <cstddef>

#define RELS   16
#define INDIM  128
#define HDIM   128
#define ODIM   64
#define NMAX   50000
#define EMAX   800000

// ---------------------------------------------------------------------------
// Scratch (__device__ globals; allocation-free rule)
// ---------------------------------------------------------------------------
__device__ float g_h[(size_t)NMAX * HDIM];                  // [N,128] ~25.6MB (L2)
__device__ __nv_bfloat16 g_w1hi[RELS * 128 * 128];          // W1^T [r][n][k]
__device__ __nv_bfloat16 g_w1lo[RELS * 128 * 128];
__device__ __nv_bfloat16 g_w2hi[RELS * 64 * 128];           // W2^T [r][n][k]
__device__ __nv_bfloat16 g_w2lo[RELS * 64 * 128];
__device__ int   g_hist[RELS];
__device__ int   g_reloff[RELS + 1];
__device__ int   g_blkoff[RELS + 1];
__device__ int   g_cursor[RELS];
__device__ int   g_srcp[EMAX];
__device__ int   g_dstp[EMAX];
__device__ float g_normp[EMAX];

// ---------------------------------------------------------------------------
// Helpers (arch-agnostic PTX: ldmatrix sm_75+, mma.bf16 sm_80+)
// ---------------------------------------------------------------------------
__device__ __forceinline__ uint32_t smem_u32(const void* p) {
    uint32_t a;
    asm("{ .reg .u64 t; cvta.to.shared.u64 t, %1; cvt.u32.u64 %0, t; }"
        : "=r"(a) : "l"(p));
    return a;
}
#define SWZ128(o) ((o) ^ (((o) >> 3) & 0x70))

__device__ __forceinline__ void ldsm4(uint32_t* r, uint32_t addr) {
    asm volatile("ldmatrix.sync.aligned.m8n8.x4.shared.b16 {%0,%1,%2,%3}, [%4];"
                 : "=r"(r[0]), "=r"(r[1]), "=r"(r[2]), "=r"(r[3]) : "r"(addr));
}
__device__ __forceinline__ void mma16816(float* d, const uint32_t* a, const uint32_t* b) {
    asm volatile("mma.sync.aligned.m16n8k16.row.col.f32.bf16.bf16.f32 "
                 "{%0,%1,%2,%3}, {%4,%5,%6,%7}, {%8,%9}, {%0,%1,%2,%3};"
                 : "+f"(d[0]), "+f"(d[1]), "+f"(d[2]), "+f"(d[3])
                 : "r"(a[0]), "r"(a[1]), "r"(a[2]), "r"(a[3]), "r"(b[0]), "r"(b[1]));
}
__device__ __forceinline__ uint32_t pack_bf16x2(float a, float b) {
    __nv_bfloat16 ha = __float2bfloat16(a), hb = __float2bfloat16(b);
    return (uint32_t)__bfloat16_as_ushort(ha) |
           ((uint32_t)__bfloat16_as_ushort(hb) << 16);
}

// ---------------------------------------------------------------------------
// Combined weight split (W1 & W2 -> transposed hi/lo bf16) + hist zero.
// ---------------------------------------------------------------------------
__global__ void splitWall(const float* __restrict__ W1, const float* __restrict__ W2,
                          __nv_bfloat16* __restrict__ w1hi, __nv_bfloat16* __restrict__ w1lo,
                          __nv_bfloat16* __restrict__ w2hi, __nv_bfloat16* __restrict__ w2lo) {
    int i = blockIdx.x * blockDim.x + threadIdx.x;
    int stride = gridDim.x * blockDim.x;
    if (i < RELS) g_hist[i] = 0;
    const int t1 = RELS * 128 * 128;
    for (int o = i; o < t1; o += stride) {
        int r = o / (128 * 128);
        int rem = o - r * 128 * 128;
        int n = rem >> 7, k = rem & 127;
        float v = W1[((size_t)r * 128 + k) * 128 + n];
        __nv_bfloat16 h = __float2bfloat16(v);
        w1hi[o] = h;
        w1lo[o] = __float2bfloat16(v - __bfloat162float(h));
    }
    const int t2 = RELS * 64 * 128;
    for (int o = i; o < t2; o += stride) {
        int r = o / (64 * 128);
        int rem = o - r * 64 * 128;
        int n = rem >> 7, k = rem & 127;
        float v = W2[((size_t)r * 128 + k) * 64 + n];
        __nv_bfloat16 h = __float2bfloat16(v);
        w2hi[o] = h;
        w2lo[o] = __float2bfloat16(v - __bfloat162float(h));
    }
}

// ---------------------------------------------------------------------------
// Edge bucket sort by etype: hist -> scan -> permute
// ---------------------------------------------------------------------------
__global__ void histk(const int* __restrict__ ety, int E) {
    __shared__ int sh[RELS];
    if (threadIdx.x < RELS) sh[threadIdx.x] = 0;
    __syncthreads();
    int e = blockIdx.x * blockDim.x + threadIdx.x;
    if (e < E) atomicAdd(&sh[ety[e]], 1);
    __syncthreads();
    if (threadIdx.x < RELS) atomicAdd(&g_hist[threadIdx.x], sh[threadIdx.x]);
}
__global__ void scank() {
    int off = 0, boff = 0;
    for (int r = 0; r < RELS; r++) {
        g_reloff[r] = off; g_blkoff[r] = boff; g_cursor[r] = off;
        int c = g_hist[r];
        off += c; boff += (c + 127) / 128;
    }
    g_reloff[RELS] = off; g_blkoff[RELS] = boff;
}
__global__ void permutek(const int* __restrict__ src, const int* __restrict__ dst,
                         const int* __restrict__ ety, const float* __restrict__ norm, int E) {
    __shared__ int sh[RELS], sbase[RELS];
    if (threadIdx.x < RELS) sh[threadIdx.x] = 0;
    __syncthreads();
    int e = blockIdx.x * blockDim.x + threadIdx.x;
    int r = 0, lr = 0;
    if (e < E) { r = ety[e]; lr = atomicAdd(&sh[r], 1); }
    __syncthreads();
    if (threadIdx.x < RELS) sbase[threadIdx.x] = atomicAdd(&g_cursor[threadIdx.x], sh[threadIdx.x]);
    __syncthreads();
    if (e < E) {
        int pos = sbase[r] + lr;
        g_srcp[pos] = src[e];
        g_dstp[pos] = dst[e];
        g_normp[pos] = norm[e];
    }
}

// ---------------------------------------------------------------------------
// Zero both accumulators in one launch.
// ---------------------------------------------------------------------------
__global__ void zeroall(float4* __restrict__ h4, int n4h, float4* __restrict__ o4, int n4o) {
    int i = blockIdx.x * blockDim.x + threadIdx.x;
    if (i < n4h) h4[i] = make_float4(0.f, 0.f, 0.f, 0.f);
    else if (i - n4h < n4o) o4[i - n4h] = make_float4(0.f, 0.f, 0.f, 0.f);
}

// ---------------------------------------------------------------------------
// Fused gather + tensor-core GEMM + scatter (R7 structure, restructured MMA).
// CTA = 128 edges of one relation. Per k-step: load each fragment ONCE
// (A_hi, A_lo, B_hi, B_lo — 12 ldsm4 vs 18 in the 3-pass form), then issue
// all 3 products' MMAs back-to-back into one fp32 accumulator.
// ---------------------------------------------------------------------------
template <int COLS, bool RELU>
__global__ __launch_bounds__(256)
void rgcn_fused(const float* __restrict__ A,
                const __nv_bfloat16* __restrict__ Whi, const __nv_bfloat16* __restrict__ Wlo,
                float* __restrict__ Out) {
    extern __shared__ char smem[];
    constexpr int ATILE = 128 * 128;      // bytes per K-subtile of A
    constexpr int BTILE = COLS * 128;     // bytes per K-subtile of B
    constexpr int A_HI = 0;
    constexpr int A_LO = 2 * ATILE;
    constexpr int B_HI = 4 * ATILE;
    constexpr int B_LO = B_HI + 2 * BTILE;
    constexpr int META = B_LO + 2 * BTILE;           // s_src,s_dst,s_norm
    constexpr int NW   = (COLS == 128) ? 64 : 32;
    constexpr int NF   = NW / 8;
    constexpr int STR  = COLS + 4;                   // staging stride (floats)
    constexpr int V4R  = COLS / 4;

    int* s_src = (int*)(smem + META);
    int* s_dst = (int*)(smem + META + 512);
    float* s_norm = (float*)(smem + META + 1024);
    float* stag = (float*)smem;                      // reuses A/B after MMA

    const uint32_t sb = smem_u32(smem);
    const int tid = threadIdx.x;
    const int wid = tid >> 5;
    const int lane = tid & 31;
    const int bid = blockIdx.x;

    // ---- map flat block -> (relation, edge tile) ----
    if (bid >= __ldg(&g_blkoff[RELS])) return;
    int r = 0;
#pragma unroll
    for (int i = 0; i < RELS; i++)
        if (bid >= __ldg(&g_blkoff[i + 1])) r = i + 1;
    const int e0 = __ldg(&g_reloff[r]) + (bid - __ldg(&g_blkoff[r])) * 128;
    const int nE = min(128, __ldg(&g_reloff[r + 1]) - e0);

    // ---- edge meta ----
    if (tid < 128) {
        bool v = tid < nE;
        s_src[tid] = v ? __ldg(&g_srcp[e0 + tid]) : 0;
        s_dst[tid] = v ? __ldg(&g_dstp[e0 + tid]) : 0;
        s_norm[tid] = v ? __ldg(&g_normp[e0 + tid]) : 0.f;
    }
    // ---- load W_r (pre-split hi/lo bf16), swizzled ----
    for (int i = tid; i < COLS * 16; i += 256) {
        int n = i >> 4, u = i & 15;
        uint32_t so = (u >> 3) * BTILE + SWZ128(n * 128 + (u & 7) * 16);
        const size_t gi = ((size_t)r * COLS + n) * 128 + u * 8;
        *(uint4*)(smem + B_HI + so) = *(const uint4*)(Whi + gi);
        *(uint4*)(smem + B_LO + so) = *(const uint4*)(Wlo + gi);
    }
    __syncthreads();   // s_src ready before gather

    // ---- gather A rows, convert fp32 -> hi/lo bf16, swizzled store ----
    for (int i = tid; i < 128 * 16; i += 256) {
        int row = i >> 4, u = i & 15;
        uint32_t so = (u >> 3) * ATILE + SWZ128(row * 128 + (u & 7) * 16);
        const float* ap = A + (size_t)s_src[row] * 128 + u * 8;
        float4 v0 = __ldg((const float4*)ap);
        float4 v1 = __ldg((const float4*)(ap + 4));
        float vs[8] = {v0.x, v0.y, v0.z, v0.w, v1.x, v1.y, v1.z, v1.w};
        if (RELU) {
#pragma unroll
            for (int j = 0; j < 8; j++) vs[j] = fmaxf(vs[j], 0.f);
        }
        uint32_t hi[4], lo[4];
#pragma unroll
        for (int j = 0; j < 4; j++) {
            float a = vs[2 * j], b = vs[2 * j + 1];
            __nv_bfloat16 ha = __float2bfloat16(a), hb = __float2bfloat16(b);
            float ra = a - __bfloat162float(ha), rb = b - __bfloat162float(hb);
            hi[j] = (uint32_t)__bfloat16_as_ushort(ha) |
                    ((uint32_t)__bfloat16_as_ushort(hb) << 16);
            lo[j] = pack_bf16x2(ra, rb);
        }
        *(uint4*)(smem + A_HI + so) = make_uint4(hi[0], hi[1], hi[2], hi[3]);
        *(uint4*)(smem + A_LO + so) = make_uint4(lo[0], lo[1], lo[2], lo[3]);
    }
    __syncthreads();

    // ---- MMA: one fragment load per k-step, 3 products fused ----
    const int wm = wid & 3;
    const int wn = wid >> 2;
    float acc[2][NF][4];
#pragma unroll
    for (int mf = 0; mf < 2; mf++)
#pragma unroll
        for (int nf = 0; nf < NF; nf++)
#pragma unroll
            for (int j = 0; j < 4; j++) acc[mf][nf][j] = 0.f;

    const int half = lane >> 4;
    const int sr = lane & 15;

#pragma unroll
    for (int ks = 0; ks < 8; ks++) {
        const int kt = ks >> 2;
        const int kb = (ks & 3) * 32;
        uint32_t ahi[2][4], alo[2][4];
#pragma unroll
        for (int mf = 0; mf < 2; mf++) {
            int row = wm * 32 + mf * 16 + sr;
            uint32_t off = kt * ATILE + SWZ128(row * 128 + kb + half * 16);
            ldsm4(ahi[mf], sb + A_HI + off);
            ldsm4(alo[mf], sb + A_LO + off);
        }
        uint32_t bhi[NF][2], blo[NF][2];
#pragma unroll
        for (int nq = 0; nq < NF / 2; nq++) {
            int n = wn * NW + nq * 16 + sr;
            uint32_t off = kt * BTILE + SWZ128(n * 128 + kb + half * 16);
            uint32_t t[4];
            ldsm4(t, sb + B_HI + off);
            bhi[nq * 2][0] = t[0]; bhi[nq * 2][1] = t[2];
            bhi[nq * 2 + 1][0] = t[1]; bhi[nq * 2 + 1][1] = t[3];
            ldsm4(t, sb + B_LO + off);
            blo[nq * 2][0] = t[0]; blo[nq * 2][1] = t[2];
            blo[nq * 2 + 1][0] = t[1]; blo[nq * 2 + 1][1] = t[3];
        }
        // hi*hi
#pragma unroll
        for (int mf = 0; mf < 2; mf++)
#pragma unroll
            for (int nf = 0; nf < NF; nf++)
                mma16816(acc[mf][nf], ahi[mf], bhi[nf]);
        // hi*lo
#pragma unroll
        for (int mf = 0; mf < 2; mf++)
#pragma unroll
            for (int nf = 0; nf < NF; nf++)
                mma16816(acc[mf][nf], ahi[mf], blo[nf]);
        // lo*hi
#pragma unroll
        for (int mf = 0; mf < 2; mf++)
#pragma unroll
            for (int nf = 0; nf < NF; nf++)
                mma16816(acc[mf][nf], alo[mf], bhi[nf]);
    }
    __syncthreads();   // A/B tiles dead; reuse as staging

    // ---- stage fp32 result into smem (conflict-free, padded stride) ----
    const int mrow = lane >> 2;
    const int mcol = (lane & 3) * 2;
#pragma unroll
    for (int mf = 0; mf < 2; mf++)
#pragma unroll
        for (int rr = 0; rr < 2; rr++) {
            int lrow = wm * 32 + mf * 16 + mrow + rr * 8;
            float* o = stag + lrow * STR + wn * NW + mcol;
#pragma unroll
            for (int nf = 0; nf < NF; nf++)
                *(float2*)(o + nf * 8) =
                    make_float2(acc[mf][nf][rr * 2], acc[mf][nf][rr * 2 + 1]);
        }
    __syncthreads();

    // ---- scale by norm, red.add.v4 into Out[dst] ----
    for (int idx = tid; idx < 128 * V4R; idx += 256) {
        int row = idx / V4R, c4 = idx % V4R;
        if (row < nE) {
            float4 v = *(float4*)(stag + row * STR + c4 * 4);
            float nm = s_norm[row];
            v.x *= nm; v.y *= nm; v.z *= nm; v.w *= nm;
            float* o = Out + (size_t)s_dst[row] * COLS + c4 * 4;
            asm volatile("red.global.add.v4.f32 [%0], {%1, %2, %3, %4};"
                         :: "l"(o), "f"(v.x), "f"(v.y), "f"(v.z), "f"(v.w) : "memory");
        }
    }
}

// ---------------------------------------------------------------------------
// Launch. Layer-1 fused kernel is launch #6.
// ---------------------------------------------------------------------------
extern "C" void kernel_launch(void* const* d_in, const int* in_sizes, int n_in,
                              void* d_out, int out_size) {
    const float* feat = (const float*)d_in[0];
    const float* norm = (const float*)d_in[1];
    const float* W1   = (const float*)d_in[2];
    const float* W2   = (const float*)d_in[3];
    const int*   src  = (const int*)d_in[4];
    const int*   dst  = (const int*)d_in[5];
    const int*   ety  = (const int*)d_in[6];
    float* out = (float*)d_out;

    const int N = in_sizes[0] / INDIM;   // 50000
    const int E = in_sizes[4];           // 800000

    float* hp;
    __nv_bfloat16 *w1hip, *w1lop, *w2hip, *w2lop;
    cudaGetSymbolAddress((void**)&hp,    g_h);
    cudaGetSymbolAddress((void**)&w1hip, g_w1hi);
    cudaGetSymbolAddress((void**)&w1lop, g_w1lo);
    cudaGetSymbolAddress((void**)&w2hip, g_w2hi);
    cudaGetSymbolAddress((void**)&w2lop, g_w2lo);

    // smem: A(64K) + B(2*BTILE*2) + meta(1.5K)
    constexpr int SM1 = 4 * 128 * 128 + 4 * 128 * 128 + 1536; // 132608
    constexpr int SM2 = 4 * 128 * 128 + 4 * 64 * 128 + 1536;  // 99840
    cudaFuncSetAttribute(rgcn_fused<128, false>,
                         cudaFuncAttributeMaxDynamicSharedMemorySize, SM1);
    cudaFuncSetAttribute(rgcn_fused<64, true>,
                         cudaFuncAttributeMaxDynamicSharedMemorySize, SM2);

    // 1. weight split (+hist zero)
    splitWall<<<1024, 256>>>(W1, W2, w1hip, w1lop, w2hip, w2lop);
    // 2-4. edge bucket sort
    const int eb = (E + 255) / 256;
    histk<<<eb, 256>>>(ety, E);
    scank<<<1, 1>>>();
    permutek<<<eb, 256>>>(src, dst, ety, norm, E);
    // 5. zero accumulators
    {
        int n4h = N * HDIM / 4, n4o = N * ODIM / 4;
        zeroall<<<(n4h + n4o + 255) / 256, 256>>>((float4*)hp, n4h, (float4*)out, n4o);
    }
    const int gB = (E + 127) / 128 + RELS;
    // 6. layer 1
    rgcn_fused<128, false><<<gB, 256, SM1>>>(feat, w1hip, w1lop, hp);
    // 7. layer 2
    rgcn_fused<64, true><<<gB, 256, SM2>>>(hp, w2hip, w2lop, out);
}

// round 14
// speedup vs baseline: 1.3629x; 1.3629x over previous
#include <cuda_runtime.h>
#include <cuda_fp16.h>
#include <cstdint>
#include <cstddef>

#define RELS   16
#define INDIM  128
#define HDIM   128
#define ODIM   64
#define NMAX   50000
#define EMAX   800000

// ---------------------------------------------------------------------------
// Scratch (__device__ globals; allocation-free rule)
// ---------------------------------------------------------------------------
__device__ float g_h[(size_t)NMAX * HDIM];                  // [N,128] ~25.6MB (L2)
__device__ __half g_w1h[RELS * 128 * 128];                  // W1^T [r][n][k] fp16
__device__ __half g_w2h[RELS * 64 * 128];                   // W2^T [r][n][k] fp16
__device__ int   g_hist[RELS];
__device__ int   g_reloff[RELS + 1];
__device__ int   g_blkoff[RELS + 1];
__device__ int   g_cursor[RELS];
__device__ int   g_srcp[EMAX];
__device__ int   g_dstp[EMAX];
__device__ float g_normp[EMAX];

// ---------------------------------------------------------------------------
// Helpers (arch-agnostic PTX: ldmatrix sm_75+, mma.f16 sm_80+)
// ---------------------------------------------------------------------------
__device__ __forceinline__ uint32_t smem_u32(const void* p) {
    uint32_t a;
    asm("{ .reg .u64 t; cvta.to.shared.u64 t, %1; cvt.u32.u64 %0, t; }"
        : "=r"(a) : "l"(p));
    return a;
}
#define SWZ128(o) ((o) ^ (((o) >> 3) & 0x70))

__device__ __forceinline__ void ldsm4(uint32_t* r, uint32_t addr) {
    asm volatile("ldmatrix.sync.aligned.m8n8.x4.shared.b16 {%0,%1,%2,%3}, [%4];"
                 : "=r"(r[0]), "=r"(r[1]), "=r"(r[2]), "=r"(r[3]) : "r"(addr));
}
__device__ __forceinline__ void mma16816(float* d, const uint32_t* a, const uint32_t* b) {
    asm volatile("mma.sync.aligned.m16n8k16.row.col.f32.f16.f16.f32 "
                 "{%0,%1,%2,%3}, {%4,%5,%6,%7}, {%8,%9}, {%0,%1,%2,%3};"
                 : "+f"(d[0]), "+f"(d[1]), "+f"(d[2]), "+f"(d[3])
                 : "r"(a[0]), "r"(a[1]), "r"(a[2]), "r"(a[3]), "r"(b[0]), "r"(b[1]));
}
__device__ __forceinline__ uint32_t h2_bits(__half2 h) {
    uint32_t u;
    *(__half2*)&u = h;
    return u;
}

// ---------------------------------------------------------------------------
// Weight split: W [R][128][NC] -> Wt [R][NC][128] single fp16 (+hist zero).
// ---------------------------------------------------------------------------
__global__ void splitWall(const float* __restrict__ W1, const float* __restrict__ W2,
                          __half* __restrict__ w1h, __half* __restrict__ w2h) {
    int i = blockIdx.x * blockDim.x + threadIdx.x;
    int stride = gridDim.x * blockDim.x;
    if (i < RELS) g_hist[i] = 0;
    const int t1 = RELS * 128 * 128;
    for (int o = i; o < t1; o += stride) {
        int r = o / (128 * 128);
        int rem = o - r * 128 * 128;
        int n = rem >> 7, k = rem & 127;
        w1h[o] = __float2half_rn(W1[((size_t)r * 128 + k) * 128 + n]);
    }
    const int t2 = RELS * 64 * 128;
    for (int o = i; o < t2; o += stride) {
        int r = o / (64 * 128);
        int rem = o - r * 64 * 128;
        int n = rem >> 7, k = rem & 127;
        w2h[o] = __float2half_rn(W2[((size_t)r * 128 + k) * 64 + n]);
    }
}

// ---------------------------------------------------------------------------
// Edge bucket sort by etype: hist -> scan -> permute
// ---------------------------------------------------------------------------
__global__ void histk(const int* __restrict__ ety, int E) {
    __shared__ int sh[RELS];
    if (threadIdx.x < RELS) sh[threadIdx.x] = 0;
    __syncthreads();
    int e = blockIdx.x * blockDim.x + threadIdx.x;
    if (e < E) atomicAdd(&sh[ety[e]], 1);
    __syncthreads();
    if (threadIdx.x < RELS) atomicAdd(&g_hist[threadIdx.x], sh[threadIdx.x]);
}
__global__ void scank() {
    int off = 0, boff = 0;
    for (int r = 0; r < RELS; r++) {
        g_reloff[r] = off; g_blkoff[r] = boff; g_cursor[r] = off;
        int c = g_hist[r];
        off += c; boff += (c + 127) / 128;
    }
    g_reloff[RELS] = off; g_blkoff[RELS] = boff;
}
__global__ void permutek(const int* __restrict__ src, const int* __restrict__ dst,
                         const int* __restrict__ ety, const float* __restrict__ norm, int E) {
    __shared__ int sh[RELS], sbase[RELS];
    if (threadIdx.x < RELS) sh[threadIdx.x] = 0;
    __syncthreads();
    int e = blockIdx.x * blockDim.x + threadIdx.x;
    int r = 0, lr = 0;
    if (e < E) { r = ety[e]; lr = atomicAdd(&sh[r], 1); }
    __syncthreads();
    if (threadIdx.x < RELS) sbase[threadIdx.x] = atomicAdd(&g_cursor[threadIdx.x], sh[threadIdx.x]);
    __syncthreads();
    if (e < E) {
        int pos = sbase[r] + lr;
        g_srcp[pos] = src[e];
        g_dstp[pos] = dst[e];
        g_normp[pos] = norm[e];
    }
}

// ---------------------------------------------------------------------------
// Zero both accumulators in one launch.
// ---------------------------------------------------------------------------
__global__ void zeroall(float4* __restrict__ h4, int n4h, float4* __restrict__ o4, int n4o) {
    int i = blockIdx.x * blockDim.x + threadIdx.x;
    if (i < n4h) h4[i] = make_float4(0.f, 0.f, 0.f, 0.f);
    else if (i - n4h < n4o) o4[i - n4h] = make_float4(0.f, 0.f, 0.f, 0.f);
}

// ---------------------------------------------------------------------------
// Fused gather + tensor-core GEMM + scatter (R7 loop structure, fp16 2-product).
// CTA = 128 edges of one relation.  A = Ahi + Alo (fp16 pair ~ fp32-exact),
// B = W fp16 (single).  D = Ahi*B + Alo*B  (2 passes).
// smem: A 64K + B 32K/16K + meta -> 2 CTAs/SM both layers.
// ---------------------------------------------------------------------------
template <int COLS, bool RELU>
__global__ __launch_bounds__(256, 2)
void rgcn_fused(const float* __restrict__ A,
                const __half* __restrict__ Wh,
                float* __restrict__ Out) {
    extern __shared__ char smem[];
    constexpr int ATILE = 128 * 128;      // bytes per K-subtile of A
    constexpr int BTILE = COLS * 128;     // bytes per K-subtile of B
    constexpr int A_HI = 0;
    constexpr int A_LO = 2 * ATILE;       // 32K
    constexpr int B_HI = 4 * ATILE;       // 64K
    constexpr int META = B_HI + 2 * BTILE;           // s_src,s_dst,s_norm
    constexpr int NW   = (COLS == 128) ? 64 : 32;
    constexpr int NF   = NW / 8;
    constexpr int STR  = COLS + 4;                   // staging stride (floats)
    constexpr int V4R  = COLS / 4;

    int* s_src = (int*)(smem + META);
    int* s_dst = (int*)(smem + META + 512);
    float* s_norm = (float*)(smem + META + 1024);
    float* stag = (float*)smem;                      // reuses A/B after MMA

    const uint32_t sb = smem_u32(smem);
    const int tid = threadIdx.x;
    const int wid = tid >> 5;
    const int lane = tid & 31;
    const int bid = blockIdx.x;

    // ---- map flat block -> (relation, edge tile) ----
    if (bid >= __ldg(&g_blkoff[RELS])) return;
    int r = 0;
#pragma unroll
    for (int i = 0; i < RELS; i++)
        if (bid >= __ldg(&g_blkoff[i + 1])) r = i + 1;
    const int e0 = __ldg(&g_reloff[r]) + (bid - __ldg(&g_blkoff[r])) * 128;
    const int nE = min(128, __ldg(&g_reloff[r + 1]) - e0);

    // ---- edge meta ----
    if (tid < 128) {
        bool v = tid < nE;
        s_src[tid] = v ? __ldg(&g_srcp[e0 + tid]) : 0;
        s_dst[tid] = v ? __ldg(&g_dstp[e0 + tid]) : 0;
        s_norm[tid] = v ? __ldg(&g_normp[e0 + tid]) : 0.f;
    }
    // ---- load W_r (fp16), swizzled ----
    for (int i = tid; i < COLS * 16; i += 256) {
        int n = i >> 4, u = i & 15;
        uint32_t so = (u >> 3) * BTILE + SWZ128(n * 128 + (u & 7) * 16);
        const size_t gi = ((size_t)r * COLS + n) * 128 + u * 8;
        *(uint4*)(smem + B_HI + so) = *(const uint4*)(Wh + gi);
    }
    __syncthreads();   // s_src ready before gather

    // ---- gather A rows, convert fp32 -> hi/lo fp16, swizzled store ----
    for (int i = tid; i < 128 * 16; i += 256) {
        int row = i >> 4, u = i & 15;
        uint32_t so = (u >> 3) * ATILE + SWZ128(row * 128 + (u & 7) * 16);
        const float* ap = A + (size_t)s_src[row] * 128 + u * 8;
        float4 v0 = __ldg((const float4*)ap);
        float4 v1 = __ldg((const float4*)(ap + 4));
        float vs[8] = {v0.x, v0.y, v0.z, v0.w, v1.x, v1.y, v1.z, v1.w};
        if (RELU) {
#pragma unroll
            for (int j = 0; j < 8; j++) vs[j] = fmaxf(vs[j], 0.f);
        }
        uint32_t hi[4], lo[4];
#pragma unroll
        for (int j = 0; j < 4; j++) {
            float a = vs[2 * j], b = vs[2 * j + 1];
            __half2 h = __float22half2_rn(make_float2(a, b));
            float2 back = __half22float2(h);
            __half2 l = __float22half2_rn(make_float2(a - back.x, b - back.y));
            hi[j] = h2_bits(h);
            lo[j] = h2_bits(l);
        }
        *(uint4*)(smem + A_HI + so) = make_uint4(hi[0], hi[1], hi[2], hi[3]);
        *(uint4*)(smem + A_LO + so) = make_uint4(lo[0], lo[1], lo[2], lo[3]);
    }
    __syncthreads();

    // ---- MMA: 2 passes (Ahi*B, Alo*B), R7 pass structure ----
    const int wm = wid & 3;
    const int wn = wid >> 2;
    float acc[2][NF][4];
#pragma unroll
    for (int mf = 0; mf < 2; mf++)
#pragma unroll
        for (int nf = 0; nf < NF; nf++)
#pragma unroll
            for (int j = 0; j < 4; j++) acc[mf][nf][j] = 0.f;

    const int half = lane >> 4;
    const int sr = lane & 15;
    const int a_off[2] = {A_HI, A_LO};

#pragma unroll
    for (int p = 0; p < 2; p++) {
        const uint32_t abase = sb + a_off[p];
        const uint32_t bbase = sb + B_HI;
#pragma unroll
        for (int ks = 0; ks < 8; ks++) {
            const int kt = ks >> 2;
            const int kb = (ks & 3) * 32;
            uint32_t a[2][4];
#pragma unroll
            for (int mf = 0; mf < 2; mf++) {
                int row = wm * 32 + mf * 16 + sr;
                ldsm4(a[mf], abase + kt * ATILE + SWZ128(row * 128 + kb + half * 16));
            }
            uint32_t b[NF][2];
#pragma unroll
            for (int nq = 0; nq < NF / 2; nq++) {
                int n = wn * NW + nq * 16 + sr;
                uint32_t t[4];
                ldsm4(t, bbase + kt * BTILE + SWZ128(n * 128 + kb + half * 16));
                b[nq * 2][0] = t[0]; b[nq * 2][1] = t[2];
                b[nq * 2 + 1][0] = t[1]; b[nq * 2 + 1][1] = t[3];
            }
#pragma unroll
            for (int mf = 0; mf < 2; mf++)
#pragma unroll
                for (int nf = 0; nf < NF; nf++)
                    mma16816(acc[mf][nf], a[mf], b[nf]);
        }
    }
    __syncthreads();   // A/B tiles dead; reuse as staging

    // ---- stage fp32 result into smem (conflict-free, padded stride) ----
    const int mrow = lane >> 2;
    const int mcol = (lane & 3) * 2;
#pragma unroll
    for (int mf = 0; mf < 2; mf++)
#pragma unroll
        for (int rr = 0; rr < 2; rr++) {
            int lrow = wm * 32 + mf * 16 + mrow + rr * 8;
            float* o = stag + lrow * STR + wn * NW + mcol;
#pragma unroll
            for (int nf = 0; nf < NF; nf++)
                *(float2*)(o + nf * 8) =
                    make_float2(acc[mf][nf][rr * 2], acc[mf][nf][rr * 2 + 1]);
        }
    __syncthreads();

    // ---- scale by norm, red.add.v4 into Out[dst] ----
    for (int idx = tid; idx < 128 * V4R; idx += 256) {
        int row = idx / V4R, c4 = idx % V4R;
        if (row < nE) {
            float4 v = *(float4*)(stag + row * STR + c4 * 4);
            float nm = s_norm[row];
            v.x *= nm; v.y *= nm; v.z *= nm; v.w *= nm;
            float* o = Out + (size_t)s_dst[row] * COLS + c4 * 4;
            asm volatile("red.global.add.v4.f32 [%0], {%1, %2, %3, %4};"
                         :: "l"(o), "f"(v.x), "f"(v.y), "f"(v.z), "f"(v.w) : "memory");
        }
    }
}

// ---------------------------------------------------------------------------
// Launch.
// ---------------------------------------------------------------------------
extern "C" void kernel_launch(void* const* d_in, const int* in_sizes, int n_in,
                              void* d_out, int out_size) {
    const float* feat = (const float*)d_in[0];
    const float* norm = (const float*)d_in[1];
    const float* W1   = (const float*)d_in[2];
    const float* W2   = (const float*)d_in[3];
    const int*   src  = (const int*)d_in[4];
    const int*   dst  = (const int*)d_in[5];
    const int*   ety  = (const int*)d_in[6];
    float* out = (float*)d_out;

    const int N = in_sizes[0] / INDIM;   // 50000
    const int E = in_sizes[4];           // 800000

    float* hp;
    __half *w1hp, *w2hp;
    cudaGetSymbolAddress((void**)&hp,   g_h);
    cudaGetSymbolAddress((void**)&w1hp, g_w1h);
    cudaGetSymbolAddress((void**)&w2hp, g_w2h);

    // smem: A(64K hi+lo) + B(2*BTILE) + meta(1.5K)
    constexpr int SM1 = 4 * 128 * 128 + 2 * 128 * 128 + 1536; // 99840  -> 2 CTAs/SM
    constexpr int SM2 = 4 * 128 * 128 + 2 * 64 * 128 + 1536;  // 83456  -> 2 CTAs/SM
    cudaFuncSetAttribute(rgcn_fused<128, false>,
                         cudaFuncAttributeMaxDynamicSharedMemorySize, SM1);
    cudaFuncSetAttribute(rgcn_fused<64, true>,
                         cudaFuncAttributeMaxDynamicSharedMemorySize, SM2);

    // 1. weight fp16 transpose (+hist zero)
    splitWall<<<1024, 256>>>(W1, W2, w1hp, w2hp);
    // 2-4. edge bucket sort
    const int eb = (E + 255) / 256;
    histk<<<eb, 256>>>(ety, E);
    scank<<<1, 1>>>();
    permutek<<<eb, 256>>>(src, dst, ety, norm, E);
    // 5. zero accumulators
    {
        int n4h = N * HDIM / 4, n4o = N * ODIM / 4;
        zeroall<<<(n4h + n4o + 255) / 256, 256>>>((float4*)hp, n4h, (float4*)out, n4o);
    }
    const int gB = (E + 127) / 128 + RELS;
    // 6. layer 1
    rgcn_fused<128, false><<<gB, 256, SM1>>>(feat, w1hp, hp);
    // 7. layer 2
    rgcn_fused<64, true><<<gB, 256, SM2>>>(hp, w2hp, out);
}

// round 16
// speedup vs baseline: 2.0529x; 1.5063x over previous
#include <cuda_runtime.h>
#include <cuda_fp16.h>
#include <cstdint>
#include <cstddef>

#define RELS   16
#define INDIM  128
#define HDIM   128
#define ODIM   64
#define NMAX   50000
#define EMAX   800000

// ---------------------------------------------------------------------------
// Scratch (__device__ globals; allocation-free rule)
// ---------------------------------------------------------------------------
__device__ float g_h[(size_t)NMAX * HDIM];                  // [N,128] ~25.6MB (L2)
__device__ __half g_w1h[RELS * 128 * 128];                  // W1^T [r][n][k] fp16
__device__ __half g_w2h[RELS * 64 * 128];                   // W2^T [r][n][k] fp16
__device__ int   g_hist[RELS];
__device__ int   g_reloff[RELS + 1];
__device__ int   g_blkoff[RELS + 1];
__device__ int   g_cursor[RELS];
__device__ int   g_srcp[EMAX];
__device__ int   g_dstp[EMAX];
__device__ float g_normp[EMAX];

// ---------------------------------------------------------------------------
// Helpers (arch-agnostic PTX: ldmatrix sm_75+, mma.f16 sm_80+)
// ---------------------------------------------------------------------------
__device__ __forceinline__ uint32_t smem_u32(const void* p) {
    uint32_t a;
    asm("{ .reg .u64 t; cvta.to.shared.u64 t, %1; cvt.u32.u64 %0, t; }"
        : "=r"(a) : "l"(p));
    return a;
}
#define SWZ128(o) ((o) ^ (((o) >> 3) & 0x70))

__device__ __forceinline__ void ldsm4(uint32_t* r, uint32_t addr) {
    asm volatile("ldmatrix.sync.aligned.m8n8.x4.shared.b16 {%0,%1,%2,%3}, [%4];"
                 : "=r"(r[0]), "=r"(r[1]), "=r"(r[2]), "=r"(r[3]) : "r"(addr));
}
__device__ __forceinline__ void mma16816(float* d, const uint32_t* a, const uint32_t* b) {
    asm volatile("mma.sync.aligned.m16n8k16.row.col.f32.f16.f16.f32 "
                 "{%0,%1,%2,%3}, {%4,%5,%6,%7}, {%8,%9}, {%0,%1,%2,%3};"
                 : "+f"(d[0]), "+f"(d[1]), "+f"(d[2]), "+f"(d[3])
                 : "r"(a[0]), "r"(a[1]), "r"(a[2]), "r"(a[3]), "r"(b[0]), "r"(b[1]));
}
__device__ __forceinline__ uint32_t h2_bits(__half2 h) {
    uint32_t u;
    *(__half2*)&u = h;
    return u;
}

// ---------------------------------------------------------------------------
// Weight split: W [R][128][NC] -> Wt [R][NC][128] single fp16 (+hist zero).
// ---------------------------------------------------------------------------
__global__ void splitWall(const float* __restrict__ W1, const float* __restrict__ W2,
                          __half* __restrict__ w1h, __half* __restrict__ w2h) {
    int i = blockIdx.x * blockDim.x + threadIdx.x;
    int stride = gridDim.x * blockDim.x;
    if (i < RELS) g_hist[i] = 0;
    const int t1 = RELS * 128 * 128;
    for (int o = i; o < t1; o += stride) {
        int r = o / (128 * 128);
        int rem = o - r * 128 * 128;
        int n = rem >> 7, k = rem & 127;
        w1h[o] = __float2half_rn(W1[((size_t)r * 128 + k) * 128 + n]);
    }
    const int t2 = RELS * 64 * 128;
    for (int o = i; o < t2; o += stride) {
        int r = o / (64 * 128);
        int rem = o - r * 64 * 128;
        int n = rem >> 7, k = rem & 127;
        w2h[o] = __float2half_rn(W2[((size_t)r * 128 + k) * 64 + n]);
    }
}

// ---------------------------------------------------------------------------
// Edge bucket sort by etype: hist -> scan -> permute
// ---------------------------------------------------------------------------
__global__ void histk(const int* __restrict__ ety, int E) {
    __shared__ int sh[RELS];
    if (threadIdx.x < RELS) sh[threadIdx.x] = 0;
    __syncthreads();
    int e = blockIdx.x * blockDim.x + threadIdx.x;
    if (e < E) atomicAdd(&sh[ety[e]], 1);
    __syncthreads();
    if (threadIdx.x < RELS) atomicAdd(&g_hist[threadIdx.x], sh[threadIdx.x]);
}
__global__ void scank() {
    int off = 0, boff = 0;
    for (int r = 0; r < RELS; r++) {
        g_reloff[r] = off; g_blkoff[r] = boff; g_cursor[r] = off;
        int c = g_hist[r];
        off += c; boff += (c + 127) / 128;
    }
    g_reloff[RELS] = off; g_blkoff[RELS] = boff;
}
__global__ void permutek(const int* __restrict__ src, const int* __restrict__ dst,
                         const int* __restrict__ ety, const float* __restrict__ norm, int E) {
    __shared__ int sh[RELS], sbase[RELS];
    if (threadIdx.x < RELS) sh[threadIdx.x] = 0;
    __syncthreads();
    int e = blockIdx.x * blockDim.x + threadIdx.x;
    int r = 0, lr = 0;
    if (e < E) { r = ety[e]; lr = atomicAdd(&sh[r], 1); }
    __syncthreads();
    if (threadIdx.x < RELS) sbase[threadIdx.x] = atomicAdd(&g_cursor[threadIdx.x], sh[threadIdx.x]);
    __syncthreads();
    if (e < E) {
        int pos = sbase[r] + lr;
        g_srcp[pos] = src[e];
        g_dstp[pos] = dst[e];
        g_normp[pos] = norm[e];
    }
}

// ---------------------------------------------------------------------------
// Zero both accumulators in one launch.
// ---------------------------------------------------------------------------
__global__ void zeroall(float4* __restrict__ h4, int n4h, float4* __restrict__ o4, int n4o) {
    int i = blockIdx.x * blockDim.x + threadIdx.x;
    if (i < n4h) h4[i] = make_float4(0.f, 0.f, 0.f, 0.f);
    else if (i - n4h < n4o) o4[i - n4h] = make_float4(0.f, 0.f, 0.f, 0.f);
}

// ---------------------------------------------------------------------------
// Fused gather + tensor-core GEMM + scatter (single fp16 product).
// CTA = 128 edges of one relation. A and B both rounded to fp16; one MMA
// pass. smem: A 32K + B 32K/16K; epilogue stages into [0, 128*COLS*4) with
// row-rotated layout (dead A/B region).
// ---------------------------------------------------------------------------
template <int COLS, bool RELU>
__global__ __launch_bounds__(256, 2)
void rgcn_fused(const float* __restrict__ A,
                const __half* __restrict__ Wh,
                float* __restrict__ Out) {
    extern __shared__ char smem[];
    constexpr int ATILE = 128 * 128;      // bytes per A K-subtile (128r x 64k x 2B) = 16K
    constexpr int BTILE = COLS * 128;     // bytes per B K-subtile
    constexpr int A_0  = 0;               // A: 2 subtiles = 32K
    constexpr int B_0  = 2 * ATILE;       // B: 2 subtiles
    constexpr int TILEEND = B_0 + 2 * BTILE;
    constexpr int STAGEEND = 128 * COLS * 4;
    constexpr int META = (TILEEND > STAGEEND) ? TILEEND : STAGEEND;
    constexpr int NW   = (COLS == 128) ? 64 : 32;
    constexpr int NF   = NW / 8;
    constexpr int CM1  = COLS - 1;
    constexpr int V4R  = COLS / 4;

    int* s_src = (int*)(smem + META);
    int* s_dst = (int*)(smem + META + 512);
    float* s_norm = (float*)(smem + META + 1024);
    float* stag = (float*)smem;                      // reuses A/B after MMA

    const uint32_t sb = smem_u32(smem);
    const int tid = threadIdx.x;
    const int wid = tid >> 5;
    const int lane = tid & 31;
    const int bid = blockIdx.x;

    // ---- map flat block -> (relation, edge tile) ----
    if (bid >= __ldg(&g_blkoff[RELS])) return;
    int r = 0;
#pragma unroll
    for (int i = 0; i < RELS; i++)
        if (bid >= __ldg(&g_blkoff[i + 1])) r = i + 1;
    const int e0 = __ldg(&g_reloff[r]) + (bid - __ldg(&g_blkoff[r])) * 128;
    const int nE = min(128, __ldg(&g_reloff[r + 1]) - e0);

    // ---- edge meta ----
    if (tid < 128) {
        bool v = tid < nE;
        s_src[tid] = v ? __ldg(&g_srcp[e0 + tid]) : 0;
        s_dst[tid] = v ? __ldg(&g_dstp[e0 + tid]) : 0;
        s_norm[tid] = v ? __ldg(&g_normp[e0 + tid]) : 0.f;
    }
    // ---- load W_r (fp16), swizzled ----
    for (int i = tid; i < COLS * 16; i += 256) {
        int n = i >> 4, u = i & 15;
        uint32_t so = (u >> 3) * BTILE + SWZ128(n * 128 + (u & 7) * 16);
        const size_t gi = ((size_t)r * COLS + n) * 128 + u * 8;
        *(uint4*)(smem + B_0 + so) = *(const uint4*)(Wh + gi);
    }
    __syncthreads();   // s_src ready before gather

    // ---- gather A rows, convert fp32 -> fp16, swizzled store ----
    for (int i = tid; i < 128 * 16; i += 256) {
        int row = i >> 4, u = i & 15;
        uint32_t so = (u >> 3) * ATILE + SWZ128(row * 128 + (u & 7) * 16);
        const float* ap = A + (size_t)s_src[row] * 128 + u * 8;
        float4 v0 = __ldg((const float4*)ap);
        float4 v1 = __ldg((const float4*)(ap + 4));
        float vs[8] = {v0.x, v0.y, v0.z, v0.w, v1.x, v1.y, v1.z, v1.w};
        if (RELU) {
#pragma unroll
            for (int j = 0; j < 8; j++) vs[j] = fmaxf(vs[j], 0.f);
        }
        uint32_t hv[4];
#pragma unroll
        for (int j = 0; j < 4; j++)
            hv[j] = h2_bits(__float22half2_rn(make_float2(vs[2 * j], vs[2 * j + 1])));
        *(uint4*)(smem + A_0 + so) = make_uint4(hv[0], hv[1], hv[2], hv[3]);
    }
    __syncthreads();

    // ---- MMA: single pass ----
    const int wm = wid & 3;
    const int wn = wid >> 2;
    float acc[2][NF][4];
#pragma unroll
    for (int mf = 0; mf < 2; mf++)
#pragma unroll
        for (int nf = 0; nf < NF; nf++)
#pragma unroll
            for (int j = 0; j < 4; j++) acc[mf][nf][j] = 0.f;

    const int half = lane >> 4;
    const int sr = lane & 15;

#pragma unroll
    for (int ks = 0; ks < 8; ks++) {
        const int kt = ks >> 2;
        const int kb = (ks & 3) * 32;
        uint32_t a[2][4];
#pragma unroll
        for (int mf = 0; mf < 2; mf++) {
            int row = wm * 32 + mf * 16 + sr;
            ldsm4(a[mf], sb + A_0 + kt * ATILE + SWZ128(row * 128 + kb + half * 16));
        }
        uint32_t b[NF][2];
#pragma unroll
        for (int nq = 0; nq < NF / 2; nq++) {
            int n = wn * NW + nq * 16 + sr;
            uint32_t t[4];
            ldsm4(t, sb + B_0 + kt * BTILE + SWZ128(n * 128 + kb + half * 16));
            b[nq * 2][0] = t[0]; b[nq * 2][1] = t[2];
            b[nq * 2 + 1][0] = t[1]; b[nq * 2 + 1][1] = t[3];
        }
#pragma unroll
        for (int mf = 0; mf < 2; mf++)
#pragma unroll
            for (int nf = 0; nf < NF; nf++)
                mma16816(acc[mf][nf], a[mf], b[nf]);
    }
    __syncthreads();   // A/B tiles dead; reuse as staging

    // ---- stage fp32 result (row-rotated, stride = COLS, no padding) ----
    const int mrow = lane >> 2;
    const int mcol = (lane & 3) * 2;
#pragma unroll
    for (int mf = 0; mf < 2; mf++)
#pragma unroll
        for (int rr = 0; rr < 2; rr++) {
            int lrow = wm * 32 + mf * 16 + mrow + rr * 8;
            int shift = (lrow * 4) & CM1;
#pragma unroll
            for (int nf = 0; nf < NF; nf++) {
                int col = wn * NW + nf * 8 + mcol;
                int scol = (col + shift) & CM1;
                *(float2*)(stag + lrow * COLS + scol) =
                    make_float2(acc[mf][nf][rr * 2], acc[mf][nf][rr * 2 + 1]);
            }
        }
    __syncthreads();

    // ---- scale by norm, red.add.v4 into Out[dst] ----
    for (int idx = tid; idx < 128 * V4R; idx += 256) {
        int row = idx / V4R, c4 = idx % V4R;
        if (row < nE) {
            int scol = (c4 * 4 + row * 4) & CM1;
            float4 v = *(float4*)(stag + row * COLS + scol);
            float nm = s_norm[row];
            v.x *= nm; v.y *= nm; v.z *= nm; v.w *= nm;
            float* o = Out + (size_t)s_dst[row] * COLS + c4 * 4;
            asm volatile("red.global.add.v4.f32 [%0], {%1, %2, %3, %4};"
                         :: "l"(o), "f"(v.x), "f"(v.y), "f"(v.z), "f"(v.w) : "memory");
        }
    }
}

// ---------------------------------------------------------------------------
// Launch.
// ---------------------------------------------------------------------------
extern "C" void kernel_launch(void* const* d_in, const int* in_sizes, int n_in,
                              void* d_out, int out_size) {
    const float* feat = (const float*)d_in[0];
    const float* norm = (const float*)d_in[1];
    const float* W1   = (const float*)d_in[2];
    const float* W2   = (const float*)d_in[3];
    const int*   src  = (const int*)d_in[4];
    const int*   dst  = (const int*)d_in[5];
    const int*   ety  = (const int*)d_in[6];
    float* out = (float*)d_out;

    const int N = in_sizes[0] / INDIM;   // 50000
    const int E = in_sizes[4];           // 800000

    float* hp;
    __half *w1hp, *w2hp;
    cudaGetSymbolAddress((void**)&hp,   g_h);
    cudaGetSymbolAddress((void**)&w1hp, g_w1h);
    cudaGetSymbolAddress((void**)&w2hp, g_w2h);

    // smem: max(tiles, staging) + meta
    constexpr int SM1 = 128 * 128 * 4 + 1536;                 // 67072
    constexpr int SM2 = (2 * 16384 + 2 * 64 * 128) + 1536;    // 50688
    cudaFuncSetAttribute(rgcn_fused<128, false>,
                         cudaFuncAttributeMaxDynamicSharedMemorySize, SM1);
    cudaFuncSetAttribute(rgcn_fused<64, true>,
                         cudaFuncAttributeMaxDynamicSharedMemorySize, SM2);

    // 1. weight fp16 transpose (+hist zero)
    splitWall<<<1024, 256>>>(W1, W2, w1hp, w2hp);
    // 2-4. edge bucket sort
    const int eb = (E + 255) / 256;
    histk<<<eb, 256>>>(ety, E);
    scank<<<1, 1>>>();
    permutek<<<eb, 256>>>(src, dst, ety, norm, E);
    // 5. zero accumulators
    {
        int n4h = N * HDIM / 4, n4o = N * ODIM / 4;
        zeroall<<<(n4h + n4o + 255) / 256, 256>>>((float4*)hp, n4h, (float4*)out, n4o);
    }
    const int gB = (E + 127) / 128 + RELS;
    // 6. layer 1
    rgcn_fused<128, false><<<gB, 256, SM1>>>(feat, w1hp, hp);
    // 7. layer 2
    rgcn_fused<64, true><<<gB, 256, SM2>>>(hp, w2hp, out);
}

// round 17
// speedup vs baseline: 2.9525x; 1.4382x over previous
#include <cuda_runtime.h>
#include <cuda_fp16.h>
#include <cstdint>
#include <cstddef>

#define RELS   16
#define INDIM  128
#define HDIM   128
#define ODIM   64
#define NMAX   50000
#define EMAX   800000

// ---------------------------------------------------------------------------
// Scratch (__device__ globals; allocation-free rule)
// ---------------------------------------------------------------------------
__device__ float g_h[(size_t)NMAX * HDIM];                  // [N,128] ~25.6MB (L2)
__device__ __half g_w1h[RELS * 128 * 128];                  // W1^T [r][n][k] fp16
__device__ __half g_w2h[RELS * 64 * 128];                   // W2^T [r][n][k] fp16
__device__ int   g_hist[RELS];
__device__ int   g_reloff[RELS + 1];
__device__ int   g_blkoff[RELS + 1];    // 128-edge tiles (layer 1)
__device__ int   g_blkoff2[RELS + 1];   // 256-edge tiles (layer 2)
__device__ int   g_cursor[RELS];
__device__ int   g_srcp[EMAX];
__device__ int   g_dstp[EMAX];
__device__ float g_normp[EMAX];

// ---------------------------------------------------------------------------
// Helpers (arch-agnostic PTX: ldmatrix sm_75+, mma.f16 sm_80+)
// ---------------------------------------------------------------------------
__device__ __forceinline__ uint32_t smem_u32(const void* p) {
    uint32_t a;
    asm("{ .reg .u64 t; cvta.to.shared.u64 t, %1; cvt.u32.u64 %0, t; }"
        : "=r"(a) : "l"(p));
    return a;
}
#define SWZ128(o) ((o) ^ (((o) >> 3) & 0x70))

__device__ __forceinline__ void ldsm4(uint32_t* r, uint32_t addr) {
    asm volatile("ldmatrix.sync.aligned.m8n8.x4.shared.b16 {%0,%1,%2,%3}, [%4];"
                 : "=r"(r[0]), "=r"(r[1]), "=r"(r[2]), "=r"(r[3]) : "r"(addr));
}
__device__ __forceinline__ void mma16816(float* d, const uint32_t* a, const uint32_t* b) {
    asm volatile("mma.sync.aligned.m16n8k16.row.col.f32.f16.f16.f32 "
                 "{%0,%1,%2,%3}, {%4,%5,%6,%7}, {%8,%9}, {%0,%1,%2,%3};"
                 : "+f"(d[0]), "+f"(d[1]), "+f"(d[2]), "+f"(d[3])
                 : "r"(a[0]), "r"(a[1]), "r"(a[2]), "r"(a[3]), "r"(b[0]), "r"(b[1]));
}
__device__ __forceinline__ uint32_t h2_bits(__half2 h) {
    uint32_t u;
    *(__half2*)&u = h;
    return u;
}

// ---------------------------------------------------------------------------
// Weight split: W [R][128][NC] -> Wt [R][NC][128] single fp16 (+hist zero).
// ---------------------------------------------------------------------------
__global__ void splitWall(const float* __restrict__ W1, const float* __restrict__ W2,
                          __half* __restrict__ w1h, __half* __restrict__ w2h) {
    int i = blockIdx.x * blockDim.x + threadIdx.x;
    int stride = gridDim.x * blockDim.x;
    if (i < RELS) g_hist[i] = 0;
    const int t1 = RELS * 128 * 128;
    for (int o = i; o < t1; o += stride) {
        int r = o / (128 * 128);
        int rem = o - r * 128 * 128;
        int n = rem >> 7, k = rem & 127;
        w1h[o] = __float2half_rn(W1[((size_t)r * 128 + k) * 128 + n]);
    }
    const int t2 = RELS * 64 * 128;
    for (int o = i; o < t2; o += stride) {
        int r = o / (64 * 128);
        int rem = o - r * 64 * 128;
        int n = rem >> 7, k = rem & 127;
        w2h[o] = __float2half_rn(W2[((size_t)r * 128 + k) * 64 + n]);
    }
}

// ---------------------------------------------------------------------------
// Edge bucket sort by etype: hist -> scan -> permute
// ---------------------------------------------------------------------------
__global__ void histk(const int* __restrict__ ety, int E) {
    __shared__ int sh[RELS];
    if (threadIdx.x < RELS) sh[threadIdx.x] = 0;
    __syncthreads();
    int e = blockIdx.x * blockDim.x + threadIdx.x;
    if (e < E) atomicAdd(&sh[ety[e]], 1);
    __syncthreads();
    if (threadIdx.x < RELS) atomicAdd(&g_hist[threadIdx.x], sh[threadIdx.x]);
}
__global__ void scank() {
    int off = 0, b1 = 0, b2 = 0;
    for (int r = 0; r < RELS; r++) {
        g_reloff[r] = off; g_blkoff[r] = b1; g_blkoff2[r] = b2; g_cursor[r] = off;
        int c = g_hist[r];
        off += c; b1 += (c + 127) / 128; b2 += (c + 255) / 256;
    }
    g_reloff[RELS] = off; g_blkoff[RELS] = b1; g_blkoff2[RELS] = b2;
}
__global__ void permutek(const int* __restrict__ src, const int* __restrict__ dst,
                         const int* __restrict__ ety, const float* __restrict__ norm, int E) {
    __shared__ int sh[RELS], sbase[RELS];
    if (threadIdx.x < RELS) sh[threadIdx.x] = 0;
    __syncthreads();
    int e = blockIdx.x * blockDim.x + threadIdx.x;
    int r = 0, lr = 0;
    if (e < E) { r = ety[e]; lr = atomicAdd(&sh[r], 1); }
    __syncthreads();
    if (threadIdx.x < RELS) sbase[threadIdx.x] = atomicAdd(&g_cursor[threadIdx.x], sh[threadIdx.x]);
    __syncthreads();
    if (e < E) {
        int pos = sbase[r] + lr;
        g_srcp[pos] = src[e];
        g_dstp[pos] = dst[e];
        g_normp[pos] = norm[e];
    }
}

// ---------------------------------------------------------------------------
// Zero both accumulators in one launch.
// ---------------------------------------------------------------------------
__global__ void zeroall(float4* __restrict__ h4, int n4h, float4* __restrict__ o4, int n4o) {
    int i = blockIdx.x * blockDim.x + threadIdx.x;
    if (i < n4h) h4[i] = make_float4(0.f, 0.f, 0.f, 0.f);
    else if (i - n4h < n4o) o4[i - n4h] = make_float4(0.f, 0.f, 0.f, 0.f);
}

// ---------------------------------------------------------------------------
// Fused gather + tensor-core GEMM + scatter (single fp16 product, norm folded
// into the gather).  CTA = EDGES edges of one relation x COLS output cols.
// Layer 1: EDGES=128, COLS=128 (4x2 warp grid).  Layer 2: EDGES=256, COLS=64
// (8x1 warp grid) — half the tiles, same per-warp MMA shape.
// ---------------------------------------------------------------------------
template <int COLS, int EDGES, bool RELU>
__global__ __launch_bounds__(256, 2)
void rgcn_fused(const float* __restrict__ A,
                const __half* __restrict__ Wh,
                float* __restrict__ Out) {
    extern __shared__ char smem[];
    constexpr int ATILE = EDGES * 128;    // bytes per A K-subtile (EDGES r x 64 k x 2B)
    constexpr int BTILE = COLS * 128;     // bytes per B K-subtile
    constexpr int A_0  = 0;
    constexpr int B_0  = 2 * ATILE;
    constexpr int TILEEND = B_0 + 2 * BTILE;
    constexpr int STAGEEND = EDGES * COLS * 4;
    constexpr int META = (TILEEND > STAGEEND) ? TILEEND : STAGEEND;
    constexpr int WMG  = EDGES / 32;                 // warp m-groups (4 or 8)
    constexpr int NW   = COLS / (8 / WMG);           // warp n-extent (64)
    constexpr int NF   = NW / 8;                     // 8
    constexpr int CM1  = COLS - 1;
    constexpr int V4R  = COLS / 4;

    int* s_src = (int*)(smem + META);
    int* s_dst = (int*)(smem + META + EDGES * 4);
    float* s_norm = (float*)(smem + META + EDGES * 8);
    float* stag = (float*)smem;                      // reuses A/B after MMA

    const uint32_t sb = smem_u32(smem);
    const int tid = threadIdx.x;
    const int wid = tid >> 5;
    const int lane = tid & 31;
    const int bid = blockIdx.x;

    // ---- map flat block -> (relation, edge tile) ----
    const int* bo = (EDGES == 128) ? g_blkoff : g_blkoff2;
    if (bid >= __ldg(&bo[RELS])) return;
    int r = 0;
#pragma unroll
    for (int i = 0; i < RELS; i++)
        if (bid >= __ldg(&bo[i + 1])) r = i + 1;
    const int e0 = __ldg(&g_reloff[r]) + (bid - __ldg(&bo[r])) * EDGES;
    const int nE = min(EDGES, __ldg(&g_reloff[r + 1]) - e0);

    // ---- edge meta ----
    if (tid < EDGES) {
        bool v = tid < nE;
        s_src[tid] = v ? __ldg(&g_srcp[e0 + tid]) : 0;
        s_dst[tid] = v ? __ldg(&g_dstp[e0 + tid]) : 0;
        s_norm[tid] = v ? __ldg(&g_normp[e0 + tid]) : 0.f;
    }
    // ---- load W_r (fp16), swizzled ----
    for (int i = tid; i < COLS * 16; i += 256) {
        int n = i >> 4, u = i & 15;
        uint32_t so = (u >> 3) * BTILE + SWZ128(n * 128 + (u & 7) * 16);
        const size_t gi = ((size_t)r * COLS + n) * 128 + u * 8;
        *(uint4*)(smem + B_0 + so) = *(const uint4*)(Wh + gi);
    }
    __syncthreads();   // s_src/s_norm ready before gather

    // ---- gather A rows, scale by norm, convert fp32 -> fp16, swizzled ----
    for (int i = tid; i < EDGES * 16; i += 256) {
        int row = i >> 4, u = i & 15;
        uint32_t so = (u >> 3) * ATILE + SWZ128(row * 128 + (u & 7) * 16);
        const float* ap = A + (size_t)s_src[row] * 128 + u * 8;
        float nm = s_norm[row];
        float4 v0 = __ldg((const float4*)ap);
        float4 v1 = __ldg((const float4*)(ap + 4));
        float vs[8] = {v0.x, v0.y, v0.z, v0.w, v1.x, v1.y, v1.z, v1.w};
        if (RELU) {
#pragma unroll
            for (int j = 0; j < 8; j++) vs[j] = fmaxf(vs[j], 0.f);
        }
#pragma unroll
        for (int j = 0; j < 8; j++) vs[j] *= nm;
        uint32_t hv[4];
#pragma unroll
        for (int j = 0; j < 4; j++)
            hv[j] = h2_bits(__float22half2_rn(make_float2(vs[2 * j], vs[2 * j + 1])));
        *(uint4*)(smem + A_0 + so) = make_uint4(hv[0], hv[1], hv[2], hv[3]);
    }
    __syncthreads();

    // ---- MMA: single pass ----
    const int wm = wid & (WMG - 1);
    const int wn = wid / WMG;
    float acc[2][NF][4];
#pragma unroll
    for (int mf = 0; mf < 2; mf++)
#pragma unroll
        for (int nf = 0; nf < NF; nf++)
#pragma unroll
            for (int j = 0; j < 4; j++) acc[mf][nf][j] = 0.f;

    const int half = lane >> 4;
    const int sr = lane & 15;

#pragma unroll
    for (int ks = 0; ks < 8; ks++) {
        const int kt = ks >> 2;
        const int kb = (ks & 3) * 32;
        uint32_t a[2][4];
#pragma unroll
        for (int mf = 0; mf < 2; mf++) {
            int row = wm * 32 + mf * 16 + sr;
            ldsm4(a[mf], sb + A_0 + kt * ATILE + SWZ128(row * 128 + kb + half * 16));
        }
        uint32_t b[NF][2];
#pragma unroll
        for (int nq = 0; nq < NF / 2; nq++) {
            int n = wn * NW + nq * 16 + sr;
            uint32_t t[4];
            ldsm4(t, sb + B_0 + kt * BTILE + SWZ128(n * 128 + kb + half * 16));
            b[nq * 2][0] = t[0]; b[nq * 2][1] = t[2];
            b[nq * 2 + 1][0] = t[1]; b[nq * 2 + 1][1] = t[3];
        }
#pragma unroll
        for (int mf = 0; mf < 2; mf++)
#pragma unroll
            for (int nf = 0; nf < NF; nf++)
                mma16816(acc[mf][nf], a[mf], b[nf]);
    }
    __syncthreads();   // A/B tiles dead; reuse as staging

    // ---- stage fp32 result (row-rotated, stride = COLS, no padding) ----
    const int mrow = lane >> 2;
    const int mcol = (lane & 3) * 2;
#pragma unroll
    for (int mf = 0; mf < 2; mf++)
#pragma unroll
        for (int rr = 0; rr < 2; rr++) {
            int lrow = wm * 32 + mf * 16 + mrow + rr * 8;
            int shift = (lrow * 4) & CM1;
#pragma unroll
            for (int nf = 0; nf < NF; nf++) {
                int col = wn * NW + nf * 8 + mcol;
                int scol = (col + shift) & CM1;
                *(float2*)(stag + lrow * COLS + scol) =
                    make_float2(acc[mf][nf][rr * 2], acc[mf][nf][rr * 2 + 1]);
            }
        }
    __syncthreads();

    // ---- red.add.v4 into Out[dst] (norm already applied) ----
    for (int idx = tid; idx < EDGES * V4R; idx += 256) {
        int row = idx / V4R, c4 = idx % V4R;
        if (row < nE) {
            int scol = (c4 * 4 + row * 4) & CM1;
            float4 v = *(float4*)(stag + row * COLS + scol);
            float* o = Out + (size_t)s_dst[row] * COLS + c4 * 4;
            asm volatile("red.global.add.v4.f32 [%0], {%1, %2, %3, %4};"
                         :: "l"(o), "f"(v.x), "f"(v.y), "f"(v.z), "f"(v.w) : "memory");
        }
    }
}

// ---------------------------------------------------------------------------
// Launch.
// ---------------------------------------------------------------------------
extern "C" void kernel_launch(void* const* d_in, const int* in_sizes, int n_in,
                              void* d_out, int out_size) {
    const float* feat = (const float*)d_in[0];
    const float* norm = (const float*)d_in[1];
    const float* W1   = (const float*)d_in[2];
    const float* W2   = (const float*)d_in[3];
    const int*   src  = (const int*)d_in[4];
    const int*   dst  = (const int*)d_in[5];
    const int*   ety  = (const int*)d_in[6];
    float* out = (float*)d_out;

    const int N = in_sizes[0] / INDIM;   // 50000
    const int E = in_sizes[4];           // 800000

    float* hp;
    __half *w1hp, *w2hp;
    cudaGetSymbolAddress((void**)&hp,   g_h);
    cudaGetSymbolAddress((void**)&w1hp, g_w1h);
    cudaGetSymbolAddress((void**)&w2hp, g_w2h);

    // smem: max(tiles, staging) + meta
    constexpr int SM1 = 128 * 128 * 4 + 128 * 12;                    // 67072
    constexpr int SM2 = (2 * 256 * 128 + 2 * 64 * 128) + 256 * 12;   // 84992
    cudaFuncSetAttribute(rgcn_fused<128, 128, false>,
                         cudaFuncAttributeMaxDynamicSharedMemorySize, SM1);
    cudaFuncSetAttribute(rgcn_fused<64, 256, true>,
                         cudaFuncAttributeMaxDynamicSharedMemorySize, SM2);

    // 1. weight fp16 transpose (+hist zero)
    splitWall<<<1024, 256>>>(W1, W2, w1hp, w2hp);
    // 2-4. edge bucket sort
    const int eb = (E + 255) / 256;
    histk<<<eb, 256>>>(ety, E);
    scank<<<1, 1>>>();
    permutek<<<eb, 256>>>(src, dst, ety, norm, E);
    // 5. zero accumulators
    {
        int n4h = N * HDIM / 4, n4o = N * ODIM / 4;
        zeroall<<<(n4h + n4o + 255) / 256, 256>>>((float4*)hp, n4h, (float4*)out, n4o);
    }
    // 6. layer 1 (128-edge tiles)
    const int gB1 = (E + 127) / 128 + RELS;
    rgcn_fused<128, 128, false><<<gB1, 256, SM1>>>(feat, w1hp, hp);
    // 7. layer 2 (256-edge tiles)
    const int gB2 = (E + 255) / 256 + RELS;
    rgcn_fused<64, 256, true><<<gB2, 256, SM2>>>(hp, w2hp, out);
}